// round 5
// baseline (speedup 1.0000x reference)
#include <cuda_runtime.h>
#include <cuda_fp16.h>
#include <mma.h>
#include <cstdint>

using namespace nvcuda;

#define D 128
#define N_NODES_MAX 100000
#define N_EDGES_MAX 3200000

// Static scratch (allocation-free rule: __device__ globals)
__device__ __half g_support[(size_t)N_NODES_MAX * D];       // 25.6 MB (fp16)
__device__ int    g_count[N_NODES_MAX];
__device__ int    g_offs[N_NODES_MAX + 1];
__device__ int    g_rank[N_EDGES_MAX];                      // per-edge rank in row
__device__ int2   g_sorted[N_EDGES_MAX];

// ---------------------------------------------------------------------------
// Kernel 0: zero the histogram
// ---------------------------------------------------------------------------
__global__ void zero_kernel(int* __restrict__ cnt, int n) {
    int i = blockIdx.x * blockDim.x + threadIdx.x;
    if (i < n) cnt[i] = 0;
}

// ---------------------------------------------------------------------------
// Kernel 1: fused histogram + rank. rank[i] = prior count of edge i's row.
// After this kernel, cnt[] holds the full histogram.
// ---------------------------------------------------------------------------
__global__ void rank_kernel(const int* __restrict__ erow,
                            int* __restrict__ cnt,
                            int* __restrict__ rank, int n_edges) {
    int i = blockIdx.x * blockDim.x + threadIdx.x;
    int n4 = n_edges >> 2;
    if (i < n4) {
        int4 r = ((const int4*)erow)[i];
        int4 k;
        k.x = atomicAdd(&cnt[r.x], 1);
        k.y = atomicAdd(&cnt[r.y], 1);
        k.z = atomicAdd(&cnt[r.z], 1);
        k.w = atomicAdd(&cnt[r.w], 1);
        ((int4*)rank)[i] = k;
    }
    if (i < (n_edges & 3)) {
        int j = n4 * 4 + i;
        rank[j] = atomicAdd(&cnt[erow[j]], 1);
    }
}

// ---------------------------------------------------------------------------
// Kernel 2: exclusive scan (single block, 1024 threads)
// ---------------------------------------------------------------------------
__global__ __launch_bounds__(1024, 1)
void scan_kernel(const int* __restrict__ cnt,
                 int* __restrict__ offs, int n) {
    __shared__ int wsum[32];
    __shared__ int carry;
    const int tid = threadIdx.x;
    const int lane = tid & 31;
    const int wid = tid >> 5;

    if (tid == 0) carry = 0;
    __syncthreads();

    for (int base = 0; base < n; base += 1024) {
        int i = base + tid;
        int v = (i < n) ? cnt[i] : 0;

        int incl = v;
#pragma unroll
        for (int d = 1; d < 32; d <<= 1) {
            int t = __shfl_up_sync(0xFFFFFFFFu, incl, d);
            if (lane >= d) incl += t;
        }
        if (lane == 31) wsum[wid] = incl;
        __syncthreads();

        if (wid == 0) {
            int w = wsum[lane];
            int s = w;
#pragma unroll
            for (int d = 1; d < 32; d <<= 1) {
                int t = __shfl_up_sync(0xFFFFFFFFu, s, d);
                if (lane >= d) s += t;
            }
            wsum[lane] = s - w;
        }
        __syncthreads();

        int excl = carry + wsum[wid] + (incl - v);
        if (i < n) offs[i] = excl;
        __syncthreads();
        if (tid == 1023) carry += wsum[31] + incl;
        __syncthreads();
    }
    if (tid == 0) offs[n] = carry;
}

// ---------------------------------------------------------------------------
// Kernel 3: atomic-free CSR scatter using precomputed ranks.
// ---------------------------------------------------------------------------
__global__ void scatter_csr_kernel(const int* __restrict__ erow,
                                   const int* __restrict__ ecol,
                                   const float* __restrict__ evals,
                                   const int* __restrict__ offs,
                                   const int* __restrict__ rank,
                                   int2* __restrict__ sorted, int n_edges) {
    int i = blockIdx.x * blockDim.x + threadIdx.x;
    int n4 = n_edges >> 2;
    if (i < n4) {
        int4 r = ((const int4*)erow)[i];
        int4 c = ((const int4*)ecol)[i];
        int4 k = ((const int4*)rank)[i];
        float4 v = ((const float4*)evals)[i];
        sorted[offs[r.x] + k.x] = make_int2(c.x, __float_as_int(v.x));
        sorted[offs[r.y] + k.y] = make_int2(c.y, __float_as_int(v.y));
        sorted[offs[r.z] + k.z] = make_int2(c.z, __float_as_int(v.z));
        sorted[offs[r.w] + k.w] = make_int2(c.w, __float_as_int(v.w));
    }
    if (i < (n_edges & 3)) {
        int j = n4 * 4 + i;
        sorted[offs[erow[j]] + rank[j]] =
            make_int2(ecol[j], __float_as_int(evals[j]));
    }
}

// ---------------------------------------------------------------------------
// Kernel 4: WMMA tensor-core GEMM: support = half(x @ W)  (unchanged)
// ---------------------------------------------------------------------------
#define LDW 136
#define SMEM_W_BYTES (128 * LDW * 2)
#define GEMM_SMEM_BYTES (SMEM_W_BYTES + 64 * LDW * 2)

__global__ __launch_bounds__(256)
void wmma_gemm_kernel(const float* __restrict__ x,
                      const float* __restrict__ w,
                      __half* __restrict__ sup, int n_rows) {
    extern __shared__ char smem[];
    __half* Wh = (__half*)smem;
    __half* Xh = (__half*)(smem + SMEM_W_BYTES);
    float*  stage = (float*)smem;

    const int tid = threadIdx.x;
    const int block_row = blockIdx.x * 64;

    for (int i = tid; i < 128 * 128 / 4; i += 256) {
        int r = (i * 4) >> 7;
        int c = (i * 4) & 127;
        float4 f = ((const float4*)w)[i];
        __half2 h[2] = { __floats2half2_rn(f.x, f.y),
                         __floats2half2_rn(f.z, f.w) };
        *(uint2*)&Wh[r * LDW + c] = *(uint2*)h;
    }
    for (int i = tid; i < 64 * 128 / 4; i += 256) {
        int r = (i * 4) >> 7;
        int c = (i * 4) & 127;
        int gr = block_row + r;
        float4 f = make_float4(0.f, 0.f, 0.f, 0.f);
        if (gr < n_rows) f = ((const float4*)x)[gr * 32 + (c >> 2)];
        __half2 h[2] = { __floats2half2_rn(f.x, f.y),
                         __floats2half2_rn(f.z, f.w) };
        *(uint2*)&Xh[r * LDW + c] = *(uint2*)h;
    }
    __syncthreads();

    const int wid = tid >> 5;
    const int wm = wid & 3;
    const int wn = wid >> 2;

    wmma::fragment<wmma::accumulator, 16, 16, 16, float> acc[4];
#pragma unroll
    for (int j = 0; j < 4; j++) wmma::fill_fragment(acc[j], 0.f);

#pragma unroll
    for (int k = 0; k < 128; k += 16) {
        wmma::fragment<wmma::matrix_a, 16, 16, 16, __half, wmma::row_major> a;
        wmma::load_matrix_sync(a, &Xh[(wm * 16) * LDW + k], LDW);
#pragma unroll
        for (int j = 0; j < 4; j++) {
            wmma::fragment<wmma::matrix_b, 16, 16, 16, __half, wmma::row_major> b;
            wmma::load_matrix_sync(b, &Wh[k * LDW + wn * 64 + j * 16], LDW);
            wmma::mma_sync(acc[j], a, b, acc[j]);
        }
    }

    __syncthreads();
#pragma unroll
    for (int j = 0; j < 4; j++)
        wmma::store_matrix_sync(&stage[(wm * 16) * 128 + wn * 64 + j * 16],
                                acc[j], 128, wmma::mem_row_major);
    __syncthreads();

    for (int i = tid; i < 64 * 128 / 8; i += 256) {
        int r = (i * 8) >> 7;
        int c = (i * 8) & 127;
        int gr = block_row + r;
        if (gr < n_rows) {
            float4 f0 = *(float4*)&stage[r * 128 + c];
            float4 f1 = *(float4*)&stage[r * 128 + c + 4];
            __half2 h[4] = { __floats2half2_rn(f0.x, f0.y),
                             __floats2half2_rn(f0.z, f0.w),
                             __floats2half2_rn(f1.x, f1.y),
                             __floats2half2_rn(f1.z, f1.w) };
            *(uint4*)&sup[(size_t)gr * D + c] = *(uint4*)h;
        }
    }
}

// ---------------------------------------------------------------------------
// Kernel 5: gather — one warp per row, 8 LDG in flight.
// ---------------------------------------------------------------------------
__device__ __forceinline__ void acc_edge(float4& acc, uint2 u, float v) {
    float2 lo = __half22float2(*(__half2*)&u.x);
    float2 hi = __half22float2(*(__half2*)&u.y);
    acc.x = fmaf(v, lo.x, acc.x);
    acc.y = fmaf(v, lo.y, acc.y);
    acc.z = fmaf(v, hi.x, acc.z);
    acc.w = fmaf(v, hi.y, acc.w);
}

__global__ __launch_bounds__(256)
void gather_kernel(const int* __restrict__ offs,
                   const int2* __restrict__ sorted,
                   const __half* __restrict__ sup,
                   const float* __restrict__ bias,
                   float* __restrict__ out, int n_rows) {
    __shared__ int2 stage[8][32];
    const int lane = threadIdx.x & 31;
    const int wloc = threadIdx.x >> 5;
    int warp = (int)((blockIdx.x * (size_t)blockDim.x + threadIdx.x) >> 5);
    const int nwarps = (int)(((size_t)gridDim.x * blockDim.x) >> 5);

    const float4 b = ((const float4*)bias)[lane];

    for (int r = warp; r < n_rows; r += nwarps) {
        const int s = offs[r];
        const int e = offs[r + 1];
        float4 acc = make_float4(0.f, 0.f, 0.f, 0.f);

        for (int base = s; base < e; base += 32) {
            int idx = base + lane;
            int2 ed = (idx < e) ? sorted[idx] : make_int2(0, 0);
            stage[wloc][lane] = ed;
            __syncwarp();
            const int m = min(32, e - base);
            int k = 0;
            for (; k + 8 <= m; k += 8) {
                int2 ee[8];
                uint2 uu[8];
#pragma unroll
                for (int j = 0; j < 8; j++) ee[j] = stage[wloc][k + j];
#pragma unroll
                for (int j = 0; j < 8; j++)
                    uu[j] = ((const uint2*)(sup + (size_t)ee[j].x * D))[lane];
#pragma unroll
                for (int j = 0; j < 8; j++)
                    acc_edge(acc, uu[j], __int_as_float(ee[j].y));
            }
            for (; k + 4 <= m; k += 4) {
                int2 ee[4];
                uint2 uu[4];
#pragma unroll
                for (int j = 0; j < 4; j++) ee[j] = stage[wloc][k + j];
#pragma unroll
                for (int j = 0; j < 4; j++)
                    uu[j] = ((const uint2*)(sup + (size_t)ee[j].x * D))[lane];
#pragma unroll
                for (int j = 0; j < 4; j++)
                    acc_edge(acc, uu[j], __int_as_float(ee[j].y));
            }
            for (; k < m; k++) {
                int2 ek = stage[wloc][k];
                uint2 u = ((const uint2*)(sup + (size_t)ek.x * D))[lane];
                acc_edge(acc, u, __int_as_float(ek.y));
            }
            __syncwarp();
        }

        float4 res = make_float4(acc.x + b.x, acc.y + b.y,
                                 acc.z + b.z, acc.w + b.w);
        ((float4*)(out + (size_t)r * D))[lane] = res;
    }
}

// ---------------------------------------------------------------------------
// Launch: CSR build on main stream, GEMM on a forked stream, join for gather.
// ---------------------------------------------------------------------------
extern "C" void kernel_launch(void* const* d_in, const int* in_sizes, int n_in,
                              void* d_out, int out_size) {
    const float* x      = (const float*)d_in[0];
    const float* weight = (const float*)d_in[1];
    const float* bias   = (const float*)d_in[2];
    const int*   erow   = (const int*)d_in[3];
    const int*   ecol   = (const int*)d_in[4];
    const float* evals  = (const float*)d_in[5];
    float* out = (float*)d_out;

    const int n_rows  = in_sizes[0] / D;
    const int n_edges = in_sizes[3];

    __half* sup;  cudaGetSymbolAddress((void**)&sup,  g_support);
    int*    cnt;  cudaGetSymbolAddress((void**)&cnt,  g_count);
    int*    offs; cudaGetSymbolAddress((void**)&offs, g_offs);
    int*    rank; cudaGetSymbolAddress((void**)&rank, g_rank);
    int2*   srt;  cudaGetSymbolAddress((void**)&srt,  g_sorted);

    // One-time resource init (first call happens outside graph capture)
    static cudaStream_t s_gemm = nullptr;
    static cudaEvent_t ev_fork = nullptr, ev_join = nullptr;
    if (s_gemm == nullptr) {
        cudaStreamCreateWithFlags(&s_gemm, cudaStreamNonBlocking);
        cudaEventCreateWithFlags(&ev_fork, cudaEventDisableTiming);
        cudaEventCreateWithFlags(&ev_join, cudaEventDisableTiming);
        cudaFuncSetAttribute(wmma_gemm_kernel,
                             cudaFuncAttributeMaxDynamicSharedMemorySize,
                             GEMM_SMEM_BYTES);
    }

    // Fork: GEMM runs concurrently with the CSR build
    cudaEventRecord(ev_fork, 0);
    cudaStreamWaitEvent(s_gemm, ev_fork, 0);
    wmma_gemm_kernel<<<(n_rows + 63) / 64, 256, GEMM_SMEM_BYTES, s_gemm>>>(
        x, weight, sup, n_rows);
    cudaEventRecord(ev_join, s_gemm);

    // CSR build (main stream)
    zero_kernel<<<(n_rows + 255) / 256, 256>>>(cnt, n_rows);
    {
        int n4 = (n_edges + 3) / 4;
        rank_kernel<<<(n4 + 255) / 256, 256>>>(erow, cnt, rank, n_edges);
    }
    scan_kernel<<<1, 1024>>>(cnt, offs, n_rows);
    {
        int n4 = (n_edges + 3) / 4;
        scatter_csr_kernel<<<(n4 + 255) / 256, 256>>>(erow, ecol, evals, offs,
                                                      rank, srt, n_edges);
    }

    // Join, then gather
    cudaStreamWaitEvent(0, ev_join, 0);
    gather_kernel<<<(n_rows + 7) / 8, 256>>>(offs, srt, sup, bias, out, n_rows);
}

// round 6
// speedup vs baseline: 1.2768x; 1.2768x over previous
#include <cuda_runtime.h>
#include <cuda_fp16.h>
#include <mma.h>
#include <cstdint>

using namespace nvcuda;

#define D 128
#define N_NODES_MAX 100000
#define N_EDGES_MAX 3200000
#define SCAN_TILE 1024

// Static scratch (allocation-free rule: __device__ globals)
__device__ __half g_support[(size_t)N_NODES_MAX * D];       // 25.6 MB (fp16)
__device__ int    g_count[N_NODES_MAX];
__device__ int    g_offs[N_NODES_MAX + 1];
__device__ int    g_rank[N_EDGES_MAX];
__device__ int2   g_sorted[N_EDGES_MAX];
__device__ int    g_partial[(N_NODES_MAX + SCAN_TILE - 1) / SCAN_TILE + 1];

// ---------------------------------------------------------------------------
// Kernel 0: zero the histogram
// ---------------------------------------------------------------------------
__global__ void zero_kernel(int* __restrict__ cnt, int n) {
    int i = blockIdx.x * blockDim.x + threadIdx.x;
    if (i < n) cnt[i] = 0;
}

// ---------------------------------------------------------------------------
// Kernel 1: fused histogram + rank. rank[i] = prior count of edge i's row.
// ---------------------------------------------------------------------------
__global__ void rank_kernel(const int* __restrict__ erow,
                            int* __restrict__ cnt,
                            int* __restrict__ rank, int n_edges) {
    int i = blockIdx.x * blockDim.x + threadIdx.x;
    int n4 = n_edges >> 2;
    if (i < n4) {
        int4 r = ((const int4*)erow)[i];
        int4 k;
        k.x = atomicAdd(&cnt[r.x], 1);
        k.y = atomicAdd(&cnt[r.y], 1);
        k.z = atomicAdd(&cnt[r.z], 1);
        k.w = atomicAdd(&cnt[r.w], 1);
        ((int4*)rank)[i] = k;
    }
    if (i < (n_edges & 3)) {
        int j = n4 * 4 + i;
        rank[j] = atomicAdd(&cnt[erow[j]], 1);
    }
}

// ---------------------------------------------------------------------------
// Scan stage A: per-block sum of SCAN_TILE counts -> partial[b]
// 256 threads, 4 ints each (int4).
// ---------------------------------------------------------------------------
__global__ __launch_bounds__(256)
void block_sum_kernel(const int* __restrict__ cnt,
                      int* __restrict__ partial, int n) {
    __shared__ int wsum[8];
    const int tid = threadIdx.x;
    const int base = blockIdx.x * SCAN_TILE + tid * 4;

    int s = 0;
    if (base + 3 < n) {
        int4 v = *(const int4*)&cnt[base];
        s = v.x + v.y + v.z + v.w;
    } else {
#pragma unroll
        for (int j = 0; j < 4; j++)
            if (base + j < n) s += cnt[base + j];
    }
#pragma unroll
    for (int d = 16; d > 0; d >>= 1)
        s += __shfl_down_sync(0xFFFFFFFFu, s, d);
    if ((tid & 31) == 0) wsum[tid >> 5] = s;
    __syncthreads();
    if (tid < 8) {
        int t = wsum[tid];
#pragma unroll
        for (int d = 4; d > 0; d >>= 1)
            t += __shfl_down_sync(0xFFu, t, d);
        if (tid == 0) partial[blockIdx.x] = t;
    }
}

// ---------------------------------------------------------------------------
// Scan stage B: single-block exclusive scan of nb partials (nb <= 1024);
// also writes offs[n] = grand total.
// ---------------------------------------------------------------------------
__global__ __launch_bounds__(1024, 1)
void scan_partials_kernel(int* __restrict__ partial,
                          int* __restrict__ offs, int nb, int n) {
    __shared__ int wsum[32];
    const int tid = threadIdx.x;
    const int lane = tid & 31;
    const int wid = tid >> 5;

    int v = (tid < nb) ? partial[tid] : 0;
    int incl = v;
#pragma unroll
    for (int d = 1; d < 32; d <<= 1) {
        int t = __shfl_up_sync(0xFFFFFFFFu, incl, d);
        if (lane >= d) incl += t;
    }
    if (lane == 31) wsum[wid] = incl;
    __syncthreads();
    if (wid == 0) {
        int w = wsum[lane];
        int s = w;
#pragma unroll
        for (int d = 1; d < 32; d <<= 1) {
            int t = __shfl_up_sync(0xFFFFFFFFu, s, d);
            if (lane >= d) s += t;
        }
        wsum[lane] = s - w;   // exclusive warp prefix
    }
    __syncthreads();
    int excl = wsum[wid] + (incl - v);
    if (tid < nb) partial[tid] = excl;
    if (tid == nb - 1) offs[n] = excl + v;   // grand total
}

// ---------------------------------------------------------------------------
// Scan stage C: per-block local exclusive scan + partial[b], writes offs.
// 256 threads x 4 contiguous ints.
// ---------------------------------------------------------------------------
__global__ __launch_bounds__(256)
void scan_final_kernel(const int* __restrict__ cnt,
                       const int* __restrict__ partial,
                       int* __restrict__ offs, int n) {
    __shared__ int wsum[8];
    const int tid = threadIdx.x;
    const int lane = tid & 31;
    const int wid = tid >> 5;
    const int base = blockIdx.x * SCAN_TILE + tid * 4;

    int v[4] = {0, 0, 0, 0};
    if (base + 3 < n) {
        int4 t = *(const int4*)&cnt[base];
        v[0] = t.x; v[1] = t.y; v[2] = t.z; v[3] = t.w;
    } else {
#pragma unroll
        for (int j = 0; j < 4; j++)
            if (base + j < n) v[j] = cnt[base + j];
    }
    int tsum = v[0] + v[1] + v[2] + v[3];

    int incl = tsum;
#pragma unroll
    for (int d = 1; d < 32; d <<= 1) {
        int t = __shfl_up_sync(0xFFFFFFFFu, incl, d);
        if (lane >= d) incl += t;
    }
    if (lane == 31) wsum[wid] = incl;
    __syncthreads();
    if (tid < 8) {
        int w = wsum[tid];
        int s = w;
#pragma unroll
        for (int d = 1; d < 8; d <<= 1) {
            int t = __shfl_up_sync(0xFFu, s, d);
            if (tid >= d) s += t;
        }
        wsum[tid] = s - w;   // exclusive warp prefix
    }
    __syncthreads();

    int excl = partial[blockIdx.x] + wsum[wid] + (incl - tsum);
    int o[4];
    o[0] = excl;
    o[1] = o[0] + v[0];
    o[2] = o[1] + v[1];
    o[3] = o[2] + v[2];
    if (base + 3 < n) {
        *(int4*)&offs[base] = make_int4(o[0], o[1], o[2], o[3]);
    } else {
#pragma unroll
        for (int j = 0; j < 4; j++)
            if (base + j < n) offs[base + j] = o[j];
    }
}

// ---------------------------------------------------------------------------
// Kernel 3: atomic-free CSR scatter using precomputed ranks.
// ---------------------------------------------------------------------------
__global__ void scatter_csr_kernel(const int* __restrict__ erow,
                                   const int* __restrict__ ecol,
                                   const float* __restrict__ evals,
                                   const int* __restrict__ offs,
                                   const int* __restrict__ rank,
                                   int2* __restrict__ sorted, int n_edges) {
    int i = blockIdx.x * blockDim.x + threadIdx.x;
    int n4 = n_edges >> 2;
    if (i < n4) {
        int4 r = ((const int4*)erow)[i];
        int4 c = ((const int4*)ecol)[i];
        int4 k = ((const int4*)rank)[i];
        float4 v = ((const float4*)evals)[i];
        sorted[offs[r.x] + k.x] = make_int2(c.x, __float_as_int(v.x));
        sorted[offs[r.y] + k.y] = make_int2(c.y, __float_as_int(v.y));
        sorted[offs[r.z] + k.z] = make_int2(c.z, __float_as_int(v.z));
        sorted[offs[r.w] + k.w] = make_int2(c.w, __float_as_int(v.w));
    }
    if (i < (n_edges & 3)) {
        int j = n4 * 4 + i;
        sorted[offs[erow[j]] + rank[j]] =
            make_int2(ecol[j], __float_as_int(evals[j]));
    }
}

// ---------------------------------------------------------------------------
// Kernel 4: WMMA tensor-core GEMM: support = half(x @ W)
// ---------------------------------------------------------------------------
#define LDW 136
#define SMEM_W_BYTES (128 * LDW * 2)
#define GEMM_SMEM_BYTES (SMEM_W_BYTES + 64 * LDW * 2)

__global__ __launch_bounds__(256)
void wmma_gemm_kernel(const float* __restrict__ x,
                      const float* __restrict__ w,
                      __half* __restrict__ sup, int n_rows) {
    extern __shared__ char smem[];
    __half* Wh = (__half*)smem;
    __half* Xh = (__half*)(smem + SMEM_W_BYTES);
    float*  stage = (float*)smem;

    const int tid = threadIdx.x;
    const int block_row = blockIdx.x * 64;

    for (int i = tid; i < 128 * 128 / 4; i += 256) {
        int r = (i * 4) >> 7;
        int c = (i * 4) & 127;
        float4 f = ((const float4*)w)[i];
        __half2 h[2] = { __floats2half2_rn(f.x, f.y),
                         __floats2half2_rn(f.z, f.w) };
        *(uint2*)&Wh[r * LDW + c] = *(uint2*)h;
    }
    for (int i = tid; i < 64 * 128 / 4; i += 256) {
        int r = (i * 4) >> 7;
        int c = (i * 4) & 127;
        int gr = block_row + r;
        float4 f = make_float4(0.f, 0.f, 0.f, 0.f);
        if (gr < n_rows) f = ((const float4*)x)[gr * 32 + (c >> 2)];
        __half2 h[2] = { __floats2half2_rn(f.x, f.y),
                         __floats2half2_rn(f.z, f.w) };
        *(uint2*)&Xh[r * LDW + c] = *(uint2*)h;
    }
    __syncthreads();

    const int wid = tid >> 5;
    const int wm = wid & 3;
    const int wn = wid >> 2;

    wmma::fragment<wmma::accumulator, 16, 16, 16, float> acc[4];
#pragma unroll
    for (int j = 0; j < 4; j++) wmma::fill_fragment(acc[j], 0.f);

#pragma unroll
    for (int k = 0; k < 128; k += 16) {
        wmma::fragment<wmma::matrix_a, 16, 16, 16, __half, wmma::row_major> a;
        wmma::load_matrix_sync(a, &Xh[(wm * 16) * LDW + k], LDW);
#pragma unroll
        for (int j = 0; j < 4; j++) {
            wmma::fragment<wmma::matrix_b, 16, 16, 16, __half, wmma::row_major> b;
            wmma::load_matrix_sync(b, &Wh[k * LDW + wn * 64 + j * 16], LDW);
            wmma::mma_sync(acc[j], a, b, acc[j]);
        }
    }

    __syncthreads();
#pragma unroll
    for (int j = 0; j < 4; j++)
        wmma::store_matrix_sync(&stage[(wm * 16) * 128 + wn * 64 + j * 16],
                                acc[j], 128, wmma::mem_row_major);
    __syncthreads();

    for (int i = tid; i < 64 * 128 / 8; i += 256) {
        int r = (i * 8) >> 7;
        int c = (i * 8) & 127;
        int gr = block_row + r;
        if (gr < n_rows) {
            float4 f0 = *(float4*)&stage[r * 128 + c];
            float4 f1 = *(float4*)&stage[r * 128 + c + 4];
            __half2 h[4] = { __floats2half2_rn(f0.x, f0.y),
                             __floats2half2_rn(f0.z, f0.w),
                             __floats2half2_rn(f1.x, f1.y),
                             __floats2half2_rn(f1.z, f1.w) };
            *(uint4*)&sup[(size_t)gr * D + c] = *(uint4*)h;
        }
    }
}

// ---------------------------------------------------------------------------
// Kernel 5: gather — one warp per row, 8 LDG in flight.
// ---------------------------------------------------------------------------
__device__ __forceinline__ void acc_edge(float4& acc, uint2 u, float v) {
    float2 lo = __half22float2(*(__half2*)&u.x);
    float2 hi = __half22float2(*(__half2*)&u.y);
    acc.x = fmaf(v, lo.x, acc.x);
    acc.y = fmaf(v, lo.y, acc.y);
    acc.z = fmaf(v, hi.x, acc.z);
    acc.w = fmaf(v, hi.y, acc.w);
}

__global__ __launch_bounds__(256)
void gather_kernel(const int* __restrict__ offs,
                   const int2* __restrict__ sorted,
                   const __half* __restrict__ sup,
                   const float* __restrict__ bias,
                   float* __restrict__ out, int n_rows) {
    __shared__ int2 stage[8][32];
    const int lane = threadIdx.x & 31;
    const int wloc = threadIdx.x >> 5;
    int warp = (int)((blockIdx.x * (size_t)blockDim.x + threadIdx.x) >> 5);
    const int nwarps = (int)(((size_t)gridDim.x * blockDim.x) >> 5);

    const float4 b = ((const float4*)bias)[lane];

    for (int r = warp; r < n_rows; r += nwarps) {
        const int s = offs[r];
        const int e = offs[r + 1];
        float4 acc = make_float4(0.f, 0.f, 0.f, 0.f);

        for (int base = s; base < e; base += 32) {
            int idx = base + lane;
            int2 ed = (idx < e) ? sorted[idx] : make_int2(0, 0);
            stage[wloc][lane] = ed;
            __syncwarp();
            const int m = min(32, e - base);
            int k = 0;
            for (; k + 8 <= m; k += 8) {
                int2 ee[8];
                uint2 uu[8];
#pragma unroll
                for (int j = 0; j < 8; j++) ee[j] = stage[wloc][k + j];
#pragma unroll
                for (int j = 0; j < 8; j++)
                    uu[j] = ((const uint2*)(sup + (size_t)ee[j].x * D))[lane];
#pragma unroll
                for (int j = 0; j < 8; j++)
                    acc_edge(acc, uu[j], __int_as_float(ee[j].y));
            }
            for (; k + 4 <= m; k += 4) {
                int2 ee[4];
                uint2 uu[4];
#pragma unroll
                for (int j = 0; j < 4; j++) ee[j] = stage[wloc][k + j];
#pragma unroll
                for (int j = 0; j < 4; j++)
                    uu[j] = ((const uint2*)(sup + (size_t)ee[j].x * D))[lane];
#pragma unroll
                for (int j = 0; j < 4; j++)
                    acc_edge(acc, uu[j], __int_as_float(ee[j].y));
            }
            for (; k < m; k++) {
                int2 ek = stage[wloc][k];
                uint2 u = ((const uint2*)(sup + (size_t)ek.x * D))[lane];
                acc_edge(acc, u, __int_as_float(ek.y));
            }
            __syncwarp();
        }

        float4 res = make_float4(acc.x + b.x, acc.y + b.y,
                                 acc.z + b.z, acc.w + b.w);
        ((float4*)(out + (size_t)r * D))[lane] = res;
    }
}

// ---------------------------------------------------------------------------
// Launch
// ---------------------------------------------------------------------------
extern "C" void kernel_launch(void* const* d_in, const int* in_sizes, int n_in,
                              void* d_out, int out_size) {
    const float* x      = (const float*)d_in[0];
    const float* weight = (const float*)d_in[1];
    const float* bias   = (const float*)d_in[2];
    const int*   erow   = (const int*)d_in[3];
    const int*   ecol   = (const int*)d_in[4];
    const float* evals  = (const float*)d_in[5];
    float* out = (float*)d_out;

    const int n_rows  = in_sizes[0] / D;
    const int n_edges = in_sizes[3];

    __half* sup;  cudaGetSymbolAddress((void**)&sup,  g_support);
    int*    cnt;  cudaGetSymbolAddress((void**)&cnt,  g_count);
    int*    offs; cudaGetSymbolAddress((void**)&offs, g_offs);
    int*    rank; cudaGetSymbolAddress((void**)&rank, g_rank);
    int2*   srt;  cudaGetSymbolAddress((void**)&srt,  g_sorted);
    int*    part; cudaGetSymbolAddress((void**)&part, g_partial);

    static cudaStream_t s_gemm = nullptr;
    static cudaEvent_t ev_fork = nullptr, ev_join = nullptr;
    if (s_gemm == nullptr) {
        cudaStreamCreateWithFlags(&s_gemm, cudaStreamNonBlocking);
        cudaEventCreateWithFlags(&ev_fork, cudaEventDisableTiming);
        cudaEventCreateWithFlags(&ev_join, cudaEventDisableTiming);
        cudaFuncSetAttribute(wmma_gemm_kernel,
                             cudaFuncAttributeMaxDynamicSharedMemorySize,
                             GEMM_SMEM_BYTES);
    }

    // Fork: GEMM runs concurrently with the CSR build
    cudaEventRecord(ev_fork, 0);
    cudaStreamWaitEvent(s_gemm, ev_fork, 0);
    wmma_gemm_kernel<<<(n_rows + 63) / 64, 256, GEMM_SMEM_BYTES, s_gemm>>>(
        x, weight, sup, n_rows);
    cudaEventRecord(ev_join, s_gemm);

    // CSR build (main stream)
    zero_kernel<<<(n_rows + 255) / 256, 256>>>(cnt, n_rows);
    {
        int n4 = (n_edges + 3) / 4;
        rank_kernel<<<(n4 + 255) / 256, 256>>>(erow, cnt, rank, n_edges);
    }
    {
        int nb = (n_rows + SCAN_TILE - 1) / SCAN_TILE;
        block_sum_kernel<<<nb, 256>>>(cnt, part, n_rows);
        scan_partials_kernel<<<1, 1024>>>(part, offs, nb, n_rows);
        scan_final_kernel<<<nb, 256>>>(cnt, part, offs, n_rows);
    }
    {
        int n4 = (n_edges + 3) / 4;
        scatter_csr_kernel<<<(n4 + 255) / 256, 256>>>(erow, ecol, evals, offs,
                                                      rank, srt, n_edges);
    }

    // Join, then gather
    cudaStreamWaitEvent(0, ev_join, 0);
    gather_kernel<<<(n_rows + 7) / 8, 256>>>(offs, srt, sup, bias, out, n_rows);
}

// round 7
// speedup vs baseline: 1.2785x; 1.0014x over previous
#include <cuda_runtime.h>
#include <cuda_fp16.h>
#include <mma.h>
#include <cstdint>

using namespace nvcuda;

#define D 128
#define N_NODES_MAX 100000
#define N_EDGES_MAX 3200000
#define SCAN_TILE 1024

// Static scratch (allocation-free rule: __device__ globals)
__device__ __half g_support[(size_t)N_NODES_MAX * D];       // 25.6 MB (fp16)
__device__ int    g_count[N_NODES_MAX];
__device__ int    g_offs[N_NODES_MAX + 1];
__device__ int    g_rank[N_EDGES_MAX];
__device__ int2   g_sorted[N_EDGES_MAX];
__device__ int    g_partial[(N_NODES_MAX + SCAN_TILE - 1) / SCAN_TILE + 1];

// ---------------------------------------------------------------------------
// Kernel 1: fused histogram + rank. rank[i] = prior count of edge i's row.
// ---------------------------------------------------------------------------
__global__ void rank_kernel(const int* __restrict__ erow,
                            int* __restrict__ cnt,
                            int* __restrict__ rank, int n_edges) {
    int i = blockIdx.x * blockDim.x + threadIdx.x;
    int n4 = n_edges >> 2;
    if (i < n4) {
        int4 r = __ldcs(&((const int4*)erow)[i]);
        int4 k;
        k.x = atomicAdd(&cnt[r.x], 1);
        k.y = atomicAdd(&cnt[r.y], 1);
        k.z = atomicAdd(&cnt[r.z], 1);
        k.w = atomicAdd(&cnt[r.w], 1);
        __stcs(&((int4*)rank)[i], k);
    }
    if (i < (n_edges & 3)) {
        int j = n4 * 4 + i;
        rank[j] = atomicAdd(&cnt[erow[j]], 1);
    }
}

// ---------------------------------------------------------------------------
// Scan stage A: per-block sum of SCAN_TILE counts -> partial[b]
// ---------------------------------------------------------------------------
__global__ __launch_bounds__(256)
void block_sum_kernel(const int* __restrict__ cnt,
                      int* __restrict__ partial, int n) {
    __shared__ int wsum[8];
    const int tid = threadIdx.x;
    const int base = blockIdx.x * SCAN_TILE + tid * 4;

    int s = 0;
    if (base + 3 < n) {
        int4 v = *(const int4*)&cnt[base];
        s = v.x + v.y + v.z + v.w;
    } else {
#pragma unroll
        for (int j = 0; j < 4; j++)
            if (base + j < n) s += cnt[base + j];
    }
#pragma unroll
    for (int d = 16; d > 0; d >>= 1)
        s += __shfl_down_sync(0xFFFFFFFFu, s, d);
    if ((tid & 31) == 0) wsum[tid >> 5] = s;
    __syncthreads();
    if (tid < 8) {
        int t = wsum[tid];
#pragma unroll
        for (int d = 4; d > 0; d >>= 1)
            t += __shfl_down_sync(0xFFu, t, d);
        if (tid == 0) partial[blockIdx.x] = t;
    }
}

// ---------------------------------------------------------------------------
// Scan stage B: single-block exclusive scan of nb partials (nb <= 1024)
// ---------------------------------------------------------------------------
__global__ __launch_bounds__(1024, 1)
void scan_partials_kernel(int* __restrict__ partial,
                          int* __restrict__ offs, int nb, int n) {
    __shared__ int wsum[32];
    const int tid = threadIdx.x;
    const int lane = tid & 31;
    const int wid = tid >> 5;

    int v = (tid < nb) ? partial[tid] : 0;
    int incl = v;
#pragma unroll
    for (int d = 1; d < 32; d <<= 1) {
        int t = __shfl_up_sync(0xFFFFFFFFu, incl, d);
        if (lane >= d) incl += t;
    }
    if (lane == 31) wsum[wid] = incl;
    __syncthreads();
    if (wid == 0) {
        int w = wsum[lane];
        int s = w;
#pragma unroll
        for (int d = 1; d < 32; d <<= 1) {
            int t = __shfl_up_sync(0xFFFFFFFFu, s, d);
            if (lane >= d) s += t;
        }
        wsum[lane] = s - w;
    }
    __syncthreads();
    int excl = wsum[wid] + (incl - v);
    if (tid < nb) partial[tid] = excl;
    if (tid == nb - 1) offs[n] = excl + v;
}

// ---------------------------------------------------------------------------
// Scan stage C: per-block local exclusive scan + partial[b], writes offs.
// ---------------------------------------------------------------------------
__global__ __launch_bounds__(256)
void scan_final_kernel(const int* __restrict__ cnt,
                       const int* __restrict__ partial,
                       int* __restrict__ offs, int n) {
    __shared__ int wsum[8];
    const int tid = threadIdx.x;
    const int lane = tid & 31;
    const int wid = tid >> 5;
    const int base = blockIdx.x * SCAN_TILE + tid * 4;

    int v[4] = {0, 0, 0, 0};
    if (base + 3 < n) {
        int4 t = *(const int4*)&cnt[base];
        v[0] = t.x; v[1] = t.y; v[2] = t.z; v[3] = t.w;
    } else {
#pragma unroll
        for (int j = 0; j < 4; j++)
            if (base + j < n) v[j] = cnt[base + j];
    }
    int tsum = v[0] + v[1] + v[2] + v[3];

    int incl = tsum;
#pragma unroll
    for (int d = 1; d < 32; d <<= 1) {
        int t = __shfl_up_sync(0xFFFFFFFFu, incl, d);
        if (lane >= d) incl += t;
    }
    if (lane == 31) wsum[wid] = incl;
    __syncthreads();
    if (tid < 8) {
        int w = wsum[tid];
        int s = w;
#pragma unroll
        for (int d = 1; d < 8; d <<= 1) {
            int t = __shfl_up_sync(0xFFu, s, d);
            if (tid >= d) s += t;
        }
        wsum[tid] = s - w;
    }
    __syncthreads();

    int excl = partial[blockIdx.x] + wsum[wid] + (incl - tsum);
    int o[4];
    o[0] = excl;
    o[1] = o[0] + v[0];
    o[2] = o[1] + v[1];
    o[3] = o[2] + v[2];
    if (base + 3 < n) {
        *(int4*)&offs[base] = make_int4(o[0], o[1], o[2], o[3]);
    } else {
#pragma unroll
        for (int j = 0; j < 4; j++)
            if (base + j < n) offs[base + j] = o[j];
    }
}

// ---------------------------------------------------------------------------
// Kernel 3: atomic-free CSR scatter using precomputed ranks.
// Streaming reads; evict-first random writes (protect L2 for support).
// ---------------------------------------------------------------------------
__global__ void scatter_csr_kernel(const int* __restrict__ erow,
                                   const int* __restrict__ ecol,
                                   const float* __restrict__ evals,
                                   const int* __restrict__ offs,
                                   const int* __restrict__ rank,
                                   int2* __restrict__ sorted, int n_edges) {
    int i = blockIdx.x * blockDim.x + threadIdx.x;
    int n4 = n_edges >> 2;
    if (i < n4) {
        int4 r = __ldcs(&((const int4*)erow)[i]);
        int4 c = __ldcs(&((const int4*)ecol)[i]);
        int4 k = __ldcs(&((const int4*)rank)[i]);
        float4 v = __ldcs(&((const float4*)evals)[i]);
        __stcs(&sorted[offs[r.x] + k.x], make_int2(c.x, __float_as_int(v.x)));
        __stcs(&sorted[offs[r.y] + k.y], make_int2(c.y, __float_as_int(v.y)));
        __stcs(&sorted[offs[r.z] + k.z], make_int2(c.z, __float_as_int(v.z)));
        __stcs(&sorted[offs[r.w] + k.w], make_int2(c.w, __float_as_int(v.w)));
    }
    if (i < (n_edges & 3)) {
        int j = n4 * 4 + i;
        sorted[offs[erow[j]] + rank[j]] =
            make_int2(ecol[j], __float_as_int(evals[j]));
    }
}

// ---------------------------------------------------------------------------
// Kernel 4: WMMA tensor-core GEMM: support = half(x @ W)
// ---------------------------------------------------------------------------
#define LDW 136
#define SMEM_W_BYTES (128 * LDW * 2)
#define GEMM_SMEM_BYTES (SMEM_W_BYTES + 64 * LDW * 2)

__global__ __launch_bounds__(256)
void wmma_gemm_kernel(const float* __restrict__ x,
                      const float* __restrict__ w,
                      __half* __restrict__ sup, int n_rows) {
    extern __shared__ char smem[];
    __half* Wh = (__half*)smem;
    __half* Xh = (__half*)(smem + SMEM_W_BYTES);
    float*  stage = (float*)smem;

    const int tid = threadIdx.x;
    const int block_row = blockIdx.x * 64;

    for (int i = tid; i < 128 * 128 / 4; i += 256) {
        int r = (i * 4) >> 7;
        int c = (i * 4) & 127;
        float4 f = ((const float4*)w)[i];
        __half2 h[2] = { __floats2half2_rn(f.x, f.y),
                         __floats2half2_rn(f.z, f.w) };
        *(uint2*)&Wh[r * LDW + c] = *(uint2*)h;
    }
    for (int i = tid; i < 64 * 128 / 4; i += 256) {
        int r = (i * 4) >> 7;
        int c = (i * 4) & 127;
        int gr = block_row + r;
        float4 f = make_float4(0.f, 0.f, 0.f, 0.f);
        if (gr < n_rows) f = __ldcs(&((const float4*)x)[gr * 32 + (c >> 2)]);
        __half2 h[2] = { __floats2half2_rn(f.x, f.y),
                         __floats2half2_rn(f.z, f.w) };
        *(uint2*)&Xh[r * LDW + c] = *(uint2*)h;
    }
    __syncthreads();

    const int wid = tid >> 5;
    const int wm = wid & 3;
    const int wn = wid >> 2;

    wmma::fragment<wmma::accumulator, 16, 16, 16, float> acc[4];
#pragma unroll
    for (int j = 0; j < 4; j++) wmma::fill_fragment(acc[j], 0.f);

#pragma unroll
    for (int k = 0; k < 128; k += 16) {
        wmma::fragment<wmma::matrix_a, 16, 16, 16, __half, wmma::row_major> a;
        wmma::load_matrix_sync(a, &Xh[(wm * 16) * LDW + k], LDW);
#pragma unroll
        for (int j = 0; j < 4; j++) {
            wmma::fragment<wmma::matrix_b, 16, 16, 16, __half, wmma::row_major> b;
            wmma::load_matrix_sync(b, &Wh[k * LDW + wn * 64 + j * 16], LDW);
            wmma::mma_sync(acc[j], a, b, acc[j]);
        }
    }

    __syncthreads();
#pragma unroll
    for (int j = 0; j < 4; j++)
        wmma::store_matrix_sync(&stage[(wm * 16) * 128 + wn * 64 + j * 16],
                                acc[j], 128, wmma::mem_row_major);
    __syncthreads();

    for (int i = tid; i < 64 * 128 / 8; i += 256) {
        int r = (i * 8) >> 7;
        int c = (i * 8) & 127;
        int gr = block_row + r;
        if (gr < n_rows) {
            float4 f0 = *(float4*)&stage[r * 128 + c];
            float4 f1 = *(float4*)&stage[r * 128 + c + 4];
            __half2 h[4] = { __floats2half2_rn(f0.x, f0.y),
                             __floats2half2_rn(f0.z, f0.w),
                             __floats2half2_rn(f1.x, f1.y),
                             __floats2half2_rn(f1.z, f1.w) };
            *(uint4*)&sup[(size_t)gr * D + c] = *(uint4*)h;
        }
    }
}

// ---------------------------------------------------------------------------
// Kernel 5: gather — one warp per row, 16 lanes per edge, 2 edges in parallel.
// Support default-cached; sorted streamed; out evict-first.
// ---------------------------------------------------------------------------
__device__ __forceinline__ void acc_u4(float4& a0, float4& a1, uint4 u, float v) {
    float2 p0 = __half22float2(*(__half2*)&u.x);
    float2 p1 = __half22float2(*(__half2*)&u.y);
    float2 p2 = __half22float2(*(__half2*)&u.z);
    float2 p3 = __half22float2(*(__half2*)&u.w);
    a0.x = fmaf(v, p0.x, a0.x); a0.y = fmaf(v, p0.y, a0.y);
    a0.z = fmaf(v, p1.x, a0.z); a0.w = fmaf(v, p1.y, a0.w);
    a1.x = fmaf(v, p2.x, a1.x); a1.y = fmaf(v, p2.y, a1.y);
    a1.z = fmaf(v, p3.x, a1.z); a1.w = fmaf(v, p3.y, a1.w);
}

__global__ __launch_bounds__(256)
void gather_kernel(const int* __restrict__ offs,
                   const int2* __restrict__ sorted,
                   const __half* __restrict__ sup,
                   const float* __restrict__ bias,
                   float* __restrict__ out, int n_rows) {
    __shared__ int2 stage[8][32];
    const int lane = threadIdx.x & 31;
    const int sub  = lane & 15;     // channel group within half-warp
    const int half = lane >> 4;     // which edge of the pair
    const int wloc = threadIdx.x >> 5;
    int warp = (int)((blockIdx.x * (size_t)blockDim.x + threadIdx.x) >> 5);
    const int nwarps = (int)(((size_t)gridDim.x * blockDim.x) >> 5);

    // lane owns channels [sub*8, sub*8+8)
    const float4 b0 = ((const float4*)bias)[sub * 2];
    const float4 b1 = ((const float4*)bias)[sub * 2 + 1];

    for (int r = warp; r < n_rows; r += nwarps) {
        const int s = offs[r];
        const int e = offs[r + 1];
        float4 a0 = make_float4(0.f, 0.f, 0.f, 0.f);
        float4 a1 = make_float4(0.f, 0.f, 0.f, 0.f);

        for (int base = s; base < e; base += 32) {
            int idx = base + lane;
            int2 ed = (idx < e) ? __ldcs(&sorted[idx]) : make_int2(0, 0);
            stage[wloc][lane] = ed;
            __syncwarp();
            const int m = min(32, e - base);
            int k = 0;
            // 8 edges per warp-iter: each half-warp does 4 with 4 LDG.128 in flight
            for (; k + 8 <= m; k += 8) {
                int2 e0 = stage[wloc][k + half];
                int2 e1 = stage[wloc][k + 2 + half];
                int2 e2 = stage[wloc][k + 4 + half];
                int2 e3 = stage[wloc][k + 6 + half];
                uint4 u0 = ((const uint4*)(sup + (size_t)e0.x * D))[sub];
                uint4 u1 = ((const uint4*)(sup + (size_t)e1.x * D))[sub];
                uint4 u2 = ((const uint4*)(sup + (size_t)e2.x * D))[sub];
                uint4 u3 = ((const uint4*)(sup + (size_t)e3.x * D))[sub];
                acc_u4(a0, a1, u0, __int_as_float(e0.y));
                acc_u4(a0, a1, u1, __int_as_float(e1.y));
                acc_u4(a0, a1, u2, __int_as_float(e2.y));
                acc_u4(a0, a1, u3, __int_as_float(e3.y));
            }
            // tail: each half takes every other remaining edge
            for (int k2 = k + half; k2 < m; k2 += 2) {
                int2 ek = stage[wloc][k2];
                uint4 u = ((const uint4*)(sup + (size_t)ek.x * D))[sub];
                acc_u4(a0, a1, u, __int_as_float(ek.y));
            }
            __syncwarp();
        }

        // combine the two half-warp partial sums (lane <-> lane^16)
        a0.x += __shfl_xor_sync(0xFFFFFFFFu, a0.x, 16);
        a0.y += __shfl_xor_sync(0xFFFFFFFFu, a0.y, 16);
        a0.z += __shfl_xor_sync(0xFFFFFFFFu, a0.z, 16);
        a0.w += __shfl_xor_sync(0xFFFFFFFFu, a0.w, 16);
        a1.x += __shfl_xor_sync(0xFFFFFFFFu, a1.x, 16);
        a1.y += __shfl_xor_sync(0xFFFFFFFFu, a1.y, 16);
        a1.z += __shfl_xor_sync(0xFFFFFFFFu, a1.z, 16);
        a1.w += __shfl_xor_sync(0xFFFFFFFFu, a1.w, 16);

        // each lane writes one float4: half 0 -> channels sub*8..+3, half 1 -> +4..+7
        float4 res;
        if (half == 0)
            res = make_float4(a0.x + b0.x, a0.y + b0.y, a0.z + b0.z, a0.w + b0.w);
        else
            res = make_float4(a1.x + b1.x, a1.y + b1.y, a1.z + b1.z, a1.w + b1.w);
        __stcs(&((float4*)(out + (size_t)r * D))[sub * 2 + half], res);
    }
}

// ---------------------------------------------------------------------------
// Launch
// ---------------------------------------------------------------------------
extern "C" void kernel_launch(void* const* d_in, const int* in_sizes, int n_in,
                              void* d_out, int out_size) {
    const float* x      = (const float*)d_in[0];
    const float* weight = (const float*)d_in[1];
    const float* bias   = (const float*)d_in[2];
    const int*   erow   = (const int*)d_in[3];
    const int*   ecol   = (const int*)d_in[4];
    const float* evals  = (const float*)d_in[5];
    float* out = (float*)d_out;

    const int n_rows  = in_sizes[0] / D;
    const int n_edges = in_sizes[3];

    __half* sup;  cudaGetSymbolAddress((void**)&sup,  g_support);
    int*    cnt;  cudaGetSymbolAddress((void**)&cnt,  g_count);
    int*    offs; cudaGetSymbolAddress((void**)&offs, g_offs);
    int*    rank; cudaGetSymbolAddress((void**)&rank, g_rank);
    int2*   srt;  cudaGetSymbolAddress((void**)&srt,  g_sorted);
    int*    part; cudaGetSymbolAddress((void**)&part, g_partial);

    static cudaStream_t s_gemm = nullptr;
    static cudaEvent_t ev_fork = nullptr, ev_join = nullptr;
    if (s_gemm == nullptr) {
        cudaStreamCreateWithFlags(&s_gemm, cudaStreamNonBlocking);
        cudaEventCreateWithFlags(&ev_fork, cudaEventDisableTiming);
        cudaEventCreateWithFlags(&ev_join, cudaEventDisableTiming);
        cudaFuncSetAttribute(wmma_gemm_kernel,
                             cudaFuncAttributeMaxDynamicSharedMemorySize,
                             GEMM_SMEM_BYTES);
    }

    // Fork: GEMM runs concurrently with the CSR build
    cudaEventRecord(ev_fork, 0);
    cudaStreamWaitEvent(s_gemm, ev_fork, 0);
    wmma_gemm_kernel<<<(n_rows + 63) / 64, 256, GEMM_SMEM_BYTES, s_gemm>>>(
        x, weight, sup, n_rows);
    cudaEventRecord(ev_join, s_gemm);

    // CSR build (main stream)
    cudaMemsetAsync(cnt, 0, (size_t)n_rows * sizeof(int), 0);
    {
        int n4 = (n_edges + 3) / 4;
        rank_kernel<<<(n4 + 255) / 256, 256>>>(erow, cnt, rank, n_edges);
    }
    {
        int nb = (n_rows + SCAN_TILE - 1) / SCAN_TILE;
        block_sum_kernel<<<nb, 256>>>(cnt, part, n_rows);
        scan_partials_kernel<<<1, 1024>>>(part, offs, nb, n_rows);
        scan_final_kernel<<<nb, 256>>>(cnt, part, offs, n_rows);
    }
    {
        int n4 = (n_edges + 3) / 4;
        scatter_csr_kernel<<<(n4 + 255) / 256, 256>>>(erow, ecol, evals, offs,
                                                      rank, srt, n_edges);
    }

    // Join, then gather
    cudaStreamWaitEvent(0, ev_join, 0);
    gather_kernel<<<(n_rows + 7) / 8, 256>>>(offs, srt, sup, bias, out, n_rows);
}

// round 8
// speedup vs baseline: 1.2953x; 1.0131x over previous
#include <cuda_runtime.h>
#include <cuda_fp16.h>
#include <mma.h>
#include <cstdint>

using namespace nvcuda;

#define D 128
#define N_NODES_MAX 100000
#define N_EDGES_MAX 3200000
#define SCAN_TILE 1024

// Static scratch (allocation-free rule: __device__ globals)
__device__ __half g_support[(size_t)N_NODES_MAX * D];       // 25.6 MB (fp16)
__device__ int    g_count[N_NODES_MAX];
__device__ int    g_offs[N_NODES_MAX + 1];
__device__ int    g_rank[N_EDGES_MAX];
__device__ int2   g_sorted[N_EDGES_MAX];
__device__ int    g_partial[(N_NODES_MAX + SCAN_TILE - 1) / SCAN_TILE + 1];

// ---------------------------------------------------------------------------
// Kernel 1: fused histogram + rank. rank[i] = prior count of edge i's row.
// ---------------------------------------------------------------------------
__global__ void rank_kernel(const int* __restrict__ erow,
                            int* __restrict__ cnt,
                            int* __restrict__ rank, int n_edges) {
    int i = blockIdx.x * blockDim.x + threadIdx.x;
    int n4 = n_edges >> 2;
    if (i < n4) {
        int4 r = __ldcs(&((const int4*)erow)[i]);
        int4 k;
        k.x = atomicAdd(&cnt[r.x], 1);
        k.y = atomicAdd(&cnt[r.y], 1);
        k.z = atomicAdd(&cnt[r.z], 1);
        k.w = atomicAdd(&cnt[r.w], 1);
        __stcs(&((int4*)rank)[i], k);
    }
    if (i < (n_edges & 3)) {
        int j = n4 * 4 + i;
        rank[j] = atomicAdd(&cnt[erow[j]], 1);
    }
}

// ---------------------------------------------------------------------------
// Scan stage A: per-block sum of SCAN_TILE counts -> partial[b]
// ---------------------------------------------------------------------------
__global__ __launch_bounds__(256)
void block_sum_kernel(const int* __restrict__ cnt,
                      int* __restrict__ partial, int n) {
    __shared__ int wsum[8];
    const int tid = threadIdx.x;
    const int base = blockIdx.x * SCAN_TILE + tid * 4;

    int s = 0;
    if (base + 3 < n) {
        int4 v = *(const int4*)&cnt[base];
        s = v.x + v.y + v.z + v.w;
    } else {
#pragma unroll
        for (int j = 0; j < 4; j++)
            if (base + j < n) s += cnt[base + j];
    }
#pragma unroll
    for (int d = 16; d > 0; d >>= 1)
        s += __shfl_down_sync(0xFFFFFFFFu, s, d);
    if ((tid & 31) == 0) wsum[tid >> 5] = s;
    __syncthreads();
    if (tid < 8) {
        int t = wsum[tid];
#pragma unroll
        for (int d = 4; d > 0; d >>= 1)
            t += __shfl_down_sync(0xFFu, t, d);
        if (tid == 0) partial[blockIdx.x] = t;
    }
}

// ---------------------------------------------------------------------------
// Scan stage B: single-block exclusive scan of nb partials (nb <= 1024)
// ---------------------------------------------------------------------------
__global__ __launch_bounds__(1024, 1)
void scan_partials_kernel(int* __restrict__ partial,
                          int* __restrict__ offs, int nb, int n) {
    __shared__ int wsum[32];
    const int tid = threadIdx.x;
    const int lane = tid & 31;
    const int wid = tid >> 5;

    int v = (tid < nb) ? partial[tid] : 0;
    int incl = v;
#pragma unroll
    for (int d = 1; d < 32; d <<= 1) {
        int t = __shfl_up_sync(0xFFFFFFFFu, incl, d);
        if (lane >= d) incl += t;
    }
    if (lane == 31) wsum[wid] = incl;
    __syncthreads();
    if (wid == 0) {
        int w = wsum[lane];
        int s = w;
#pragma unroll
        for (int d = 1; d < 32; d <<= 1) {
            int t = __shfl_up_sync(0xFFFFFFFFu, s, d);
            if (lane >= d) s += t;
        }
        wsum[lane] = s - w;
    }
    __syncthreads();
    int excl = wsum[wid] + (incl - v);
    if (tid < nb) partial[tid] = excl;
    if (tid == nb - 1) offs[n] = excl + v;
}

// ---------------------------------------------------------------------------
// Scan stage C: per-block local exclusive scan + partial[b], writes offs.
// ---------------------------------------------------------------------------
__global__ __launch_bounds__(256)
void scan_final_kernel(const int* __restrict__ cnt,
                       const int* __restrict__ partial,
                       int* __restrict__ offs, int n) {
    __shared__ int wsum[8];
    const int tid = threadIdx.x;
    const int lane = tid & 31;
    const int wid = tid >> 5;
    const int base = blockIdx.x * SCAN_TILE + tid * 4;

    int v[4] = {0, 0, 0, 0};
    if (base + 3 < n) {
        int4 t = *(const int4*)&cnt[base];
        v[0] = t.x; v[1] = t.y; v[2] = t.z; v[3] = t.w;
    } else {
#pragma unroll
        for (int j = 0; j < 4; j++)
            if (base + j < n) v[j] = cnt[base + j];
    }
    int tsum = v[0] + v[1] + v[2] + v[3];

    int incl = tsum;
#pragma unroll
    for (int d = 1; d < 32; d <<= 1) {
        int t = __shfl_up_sync(0xFFFFFFFFu, incl, d);
        if (lane >= d) incl += t;
    }
    if (lane == 31) wsum[wid] = incl;
    __syncthreads();
    if (tid < 8) {
        int w = wsum[tid];
        int s = w;
#pragma unroll
        for (int d = 1; d < 8; d <<= 1) {
            int t = __shfl_up_sync(0xFFu, s, d);
            if (tid >= d) s += t;
        }
        wsum[tid] = s - w;
    }
    __syncthreads();

    int excl = partial[blockIdx.x] + wsum[wid] + (incl - tsum);
    int o[4];
    o[0] = excl;
    o[1] = o[0] + v[0];
    o[2] = o[1] + v[1];
    o[3] = o[2] + v[2];
    if (base + 3 < n) {
        *(int4*)&offs[base] = make_int4(o[0], o[1], o[2], o[3]);
    } else {
#pragma unroll
        for (int j = 0; j < 4; j++)
            if (base + j < n) offs[base + j] = o[j];
    }
}

// ---------------------------------------------------------------------------
// Kernel 3: atomic-free CSR scatter using precomputed ranks.
// ---------------------------------------------------------------------------
__global__ void scatter_csr_kernel(const int* __restrict__ erow,
                                   const int* __restrict__ ecol,
                                   const float* __restrict__ evals,
                                   const int* __restrict__ offs,
                                   const int* __restrict__ rank,
                                   int2* __restrict__ sorted, int n_edges) {
    int i = blockIdx.x * blockDim.x + threadIdx.x;
    int n4 = n_edges >> 2;
    if (i < n4) {
        int4 r = __ldcs(&((const int4*)erow)[i]);
        int4 c = __ldcs(&((const int4*)ecol)[i]);
        int4 k = __ldcs(&((const int4*)rank)[i]);
        float4 v = __ldcs(&((const float4*)evals)[i]);
        __stcs(&sorted[offs[r.x] + k.x], make_int2(c.x, __float_as_int(v.x)));
        __stcs(&sorted[offs[r.y] + k.y], make_int2(c.y, __float_as_int(v.y)));
        __stcs(&sorted[offs[r.z] + k.z], make_int2(c.z, __float_as_int(v.z)));
        __stcs(&sorted[offs[r.w] + k.w], make_int2(c.w, __float_as_int(v.w)));
    }
    if (i < (n_edges & 3)) {
        int j = n4 * 4 + i;
        sorted[offs[erow[j]] + rank[j]] =
            make_int2(ecol[j], __float_as_int(evals[j]));
    }
}

// ---------------------------------------------------------------------------
// Kernel 4: WMMA tensor-core GEMM: support = half(x @ W)
// ---------------------------------------------------------------------------
#define LDW 136
#define SMEM_W_BYTES (128 * LDW * 2)
#define GEMM_SMEM_BYTES (SMEM_W_BYTES + 64 * LDW * 2)

__global__ __launch_bounds__(256)
void wmma_gemm_kernel(const float* __restrict__ x,
                      const float* __restrict__ w,
                      __half* __restrict__ sup, int n_rows) {
    extern __shared__ char smem[];
    __half* Wh = (__half*)smem;
    __half* Xh = (__half*)(smem + SMEM_W_BYTES);
    float*  stage = (float*)smem;

    const int tid = threadIdx.x;
    const int block_row = blockIdx.x * 64;

    for (int i = tid; i < 128 * 128 / 4; i += 256) {
        int r = (i * 4) >> 7;
        int c = (i * 4) & 127;
        float4 f = ((const float4*)w)[i];
        __half2 h[2] = { __floats2half2_rn(f.x, f.y),
                         __floats2half2_rn(f.z, f.w) };
        *(uint2*)&Wh[r * LDW + c] = *(uint2*)h;
    }
    for (int i = tid; i < 64 * 128 / 4; i += 256) {
        int r = (i * 4) >> 7;
        int c = (i * 4) & 127;
        int gr = block_row + r;
        float4 f = make_float4(0.f, 0.f, 0.f, 0.f);
        if (gr < n_rows) f = __ldcs(&((const float4*)x)[gr * 32 + (c >> 2)]);
        __half2 h[2] = { __floats2half2_rn(f.x, f.y),
                         __floats2half2_rn(f.z, f.w) };
        *(uint2*)&Xh[r * LDW + c] = *(uint2*)h;
    }
    __syncthreads();

    const int wid = tid >> 5;
    const int wm = wid & 3;
    const int wn = wid >> 2;

    wmma::fragment<wmma::accumulator, 16, 16, 16, float> acc[4];
#pragma unroll
    for (int j = 0; j < 4; j++) wmma::fill_fragment(acc[j], 0.f);

#pragma unroll
    for (int k = 0; k < 128; k += 16) {
        wmma::fragment<wmma::matrix_a, 16, 16, 16, __half, wmma::row_major> a;
        wmma::load_matrix_sync(a, &Xh[(wm * 16) * LDW + k], LDW);
#pragma unroll
        for (int j = 0; j < 4; j++) {
            wmma::fragment<wmma::matrix_b, 16, 16, 16, __half, wmma::row_major> b;
            wmma::load_matrix_sync(b, &Wh[k * LDW + wn * 64 + j * 16], LDW);
            wmma::mma_sync(acc[j], a, b, acc[j]);
        }
    }

    __syncthreads();
#pragma unroll
    for (int j = 0; j < 4; j++)
        wmma::store_matrix_sync(&stage[(wm * 16) * 128 + wn * 64 + j * 16],
                                acc[j], 128, wmma::mem_row_major);
    __syncthreads();

    for (int i = tid; i < 64 * 128 / 8; i += 256) {
        int r = (i * 8) >> 7;
        int c = (i * 8) & 127;
        int gr = block_row + r;
        if (gr < n_rows) {
            float4 f0 = *(float4*)&stage[r * 128 + c];
            float4 f1 = *(float4*)&stage[r * 128 + c + 4];
            __half2 h[4] = { __floats2half2_rn(f0.x, f0.y),
                             __floats2half2_rn(f0.z, f0.w),
                             __floats2half2_rn(f1.x, f1.y),
                             __floats2half2_rn(f1.z, f1.w) };
            *(uint4*)&sup[(size_t)gr * D + c] = *(uint4*)h;
        }
    }
}

// ---------------------------------------------------------------------------
// Kernel 5: gather — HALF-WARP per row. 16 lanes x uint4 = full 256B row.
// Two independent rows per warp; no cross-half combine.
// ---------------------------------------------------------------------------
__device__ __forceinline__ void acc_u4(float4& a0, float4& a1, uint4 u, float v) {
    float2 p0 = __half22float2(*(__half2*)&u.x);
    float2 p1 = __half22float2(*(__half2*)&u.y);
    float2 p2 = __half22float2(*(__half2*)&u.z);
    float2 p3 = __half22float2(*(__half2*)&u.w);
    a0.x = fmaf(v, p0.x, a0.x); a0.y = fmaf(v, p0.y, a0.y);
    a0.z = fmaf(v, p1.x, a0.z); a0.w = fmaf(v, p1.y, a0.w);
    a1.x = fmaf(v, p2.x, a1.x); a1.y = fmaf(v, p2.y, a1.y);
    a1.z = fmaf(v, p3.x, a1.z); a1.w = fmaf(v, p3.y, a1.w);
}

__global__ __launch_bounds__(256)
void gather_kernel(const int* __restrict__ offs,
                   const int2* __restrict__ sorted,
                   const __half* __restrict__ sup,
                   const float* __restrict__ bias,
                   float* __restrict__ out, int n_rows) {
    __shared__ int2 stage[16][16];   // 8 warps x 2 halves, 16-edge windows
    const int lane = threadIdx.x & 31;
    const int sub  = lane & 15;          // lane within half-warp
    const int half = lane >> 4;          // 0 or 1
    const unsigned hmask = half ? 0xFFFF0000u : 0x0000FFFFu;
    const int sidx = ((threadIdx.x >> 5) << 1) | half;   // stage slot
    int warp = (int)((blockIdx.x * (size_t)blockDim.x + threadIdx.x) >> 5);
    const int nhw = (int)(((size_t)gridDim.x * blockDim.x) >> 4);  // #half-warps
    const int hw = warp * 2 + half;

    // lane owns channels [sub*8, sub*8+8)
    const float4 b0 = ((const float4*)bias)[sub * 2];
    const float4 b1 = ((const float4*)bias)[sub * 2 + 1];

    for (int r = hw; r < n_rows; r += nhw) {
        const int s = offs[r];
        const int e = offs[r + 1];
        float4 a0 = make_float4(0.f, 0.f, 0.f, 0.f);
        float4 a1 = make_float4(0.f, 0.f, 0.f, 0.f);

        for (int base = s; base < e; base += 16) {
            int idx = base + sub;
            int2 ed = (idx < e) ? __ldcs(&sorted[idx]) : make_int2(0, 0);
            stage[sidx][sub] = ed;
            __syncwarp(hmask);
            const int m = min(16, e - base);
            int k = 0;
            for (; k + 8 <= m; k += 8) {
                int2 ee[8];
                uint4 uu[8];
#pragma unroll
                for (int j = 0; j < 8; j++) ee[j] = stage[sidx][k + j];
#pragma unroll
                for (int j = 0; j < 8; j++)
                    uu[j] = ((const uint4*)(sup + (size_t)ee[j].x * D))[sub];
#pragma unroll
                for (int j = 0; j < 8; j++)
                    acc_u4(a0, a1, uu[j], __int_as_float(ee[j].y));
            }
            for (; k + 4 <= m; k += 4) {
                int2 ee[4];
                uint4 uu[4];
#pragma unroll
                for (int j = 0; j < 4; j++) ee[j] = stage[sidx][k + j];
#pragma unroll
                for (int j = 0; j < 4; j++)
                    uu[j] = ((const uint4*)(sup + (size_t)ee[j].x * D))[sub];
#pragma unroll
                for (int j = 0; j < 4; j++)
                    acc_u4(a0, a1, uu[j], __int_as_float(ee[j].y));
            }
            for (; k < m; k++) {
                int2 ek = stage[sidx][k];
                uint4 u = ((const uint4*)(sup + (size_t)ek.x * D))[sub];
                acc_u4(a0, a1, u, __int_as_float(ek.y));
            }
            __syncwarp(hmask);
        }

        float4 r0 = make_float4(a0.x + b0.x, a0.y + b0.y,
                                a0.z + b0.z, a0.w + b0.w);
        float4 r1 = make_float4(a1.x + b1.x, a1.y + b1.y,
                                a1.z + b1.z, a1.w + b1.w);
        float4* dst = (float4*)(out + (size_t)r * D);
        __stcs(&dst[sub * 2], r0);
        __stcs(&dst[sub * 2 + 1], r1);
    }
}

// ---------------------------------------------------------------------------
// Launch
// ---------------------------------------------------------------------------
extern "C" void kernel_launch(void* const* d_in, const int* in_sizes, int n_in,
                              void* d_out, int out_size) {
    const float* x      = (const float*)d_in[0];
    const float* weight = (const float*)d_in[1];
    const float* bias   = (const float*)d_in[2];
    const int*   erow   = (const int*)d_in[3];
    const int*   ecol   = (const int*)d_in[4];
    const float* evals  = (const float*)d_in[5];
    float* out = (float*)d_out;

    const int n_rows  = in_sizes[0] / D;
    const int n_edges = in_sizes[3];

    __half* sup;  cudaGetSymbolAddress((void**)&sup,  g_support);
    int*    cnt;  cudaGetSymbolAddress((void**)&cnt,  g_count);
    int*    offs; cudaGetSymbolAddress((void**)&offs, g_offs);
    int*    rank; cudaGetSymbolAddress((void**)&rank, g_rank);
    int2*   srt;  cudaGetSymbolAddress((void**)&srt,  g_sorted);
    int*    part; cudaGetSymbolAddress((void**)&part, g_partial);

    static cudaStream_t s_gemm = nullptr;
    static cudaEvent_t ev_fork = nullptr, ev_join = nullptr;
    if (s_gemm == nullptr) {
        cudaStreamCreateWithFlags(&s_gemm, cudaStreamNonBlocking);
        cudaEventCreateWithFlags(&ev_fork, cudaEventDisableTiming);
        cudaEventCreateWithFlags(&ev_join, cudaEventDisableTiming);
        cudaFuncSetAttribute(wmma_gemm_kernel,
                             cudaFuncAttributeMaxDynamicSharedMemorySize,
                             GEMM_SMEM_BYTES);
    }

    // Fork: GEMM runs concurrently with the CSR build
    cudaEventRecord(ev_fork, 0);
    cudaStreamWaitEvent(s_gemm, ev_fork, 0);
    wmma_gemm_kernel<<<(n_rows + 63) / 64, 256, GEMM_SMEM_BYTES, s_gemm>>>(
        x, weight, sup, n_rows);
    cudaEventRecord(ev_join, s_gemm);

    // CSR build (main stream)
    cudaMemsetAsync(cnt, 0, (size_t)n_rows * sizeof(int), 0);
    {
        int n4 = (n_edges + 3) / 4;
        rank_kernel<<<(n4 + 255) / 256, 256>>>(erow, cnt, rank, n_edges);
    }
    {
        int nb = (n_rows + SCAN_TILE - 1) / SCAN_TILE;
        block_sum_kernel<<<nb, 256>>>(cnt, part, n_rows);
        scan_partials_kernel<<<1, 1024>>>(part, offs, nb, n_rows);
        scan_final_kernel<<<nb, 256>>>(cnt, part, offs, n_rows);
    }
    {
        int n4 = (n_edges + 3) / 4;
        scatter_csr_kernel<<<(n4 + 255) / 256, 256>>>(erow, ecol, evals, offs,
                                                      rank, srt, n_edges);
    }

    // Join, then gather
    cudaStreamWaitEvent(0, ev_join, 0);
    gather_kernel<<<(n_rows + 15) / 16, 256>>>(offs, srt, sup, bias, out,
                                               n_rows);
}

// round 9
// speedup vs baseline: 1.4960x; 1.1549x over previous
#include <cuda_runtime.h>
#include <cuda_fp16.h>
#include <mma.h>
#include <cstdint>

using namespace nvcuda;

#define D 128
#define N_NODES_MAX 100000
#define N_EDGES_MAX 3200000
#define SCAN_TILE 1024

// Static scratch (allocation-free rule: __device__ globals)
__device__ __half g_support[(size_t)N_NODES_MAX * D];       // 25.6 MB (fp16)
__device__ int    g_count[N_NODES_MAX];
__device__ int    g_offs[N_NODES_MAX + 1];
__device__ int    g_cursor[N_NODES_MAX];
__device__ int2   g_sorted[N_EDGES_MAX];
__device__ int    g_partial[(N_NODES_MAX + SCAN_TILE - 1) / SCAN_TILE + 1];

// ---------------------------------------------------------------------------
// Kernel 1: histogram of edge_row (int4 vectorized, REDs — no return value)
// ---------------------------------------------------------------------------
__global__ void hist_kernel(const int* __restrict__ erow,
                            int* __restrict__ cnt, int n_edges) {
    int i = blockIdx.x * blockDim.x + threadIdx.x;
    int n4 = n_edges >> 2;
    if (i < n4) {
        int4 r = __ldcs(&((const int4*)erow)[i]);
        atomicAdd(&cnt[r.x], 1);
        atomicAdd(&cnt[r.y], 1);
        atomicAdd(&cnt[r.z], 1);
        atomicAdd(&cnt[r.w], 1);
    }
    if (i < (n_edges & 3)) {
        atomicAdd(&cnt[erow[n4 * 4 + i]], 1);
    }
}

// ---------------------------------------------------------------------------
// Scan stage A: per-block sum of SCAN_TILE counts -> partial[b]
// ---------------------------------------------------------------------------
__global__ __launch_bounds__(256)
void block_sum_kernel(const int* __restrict__ cnt,
                      int* __restrict__ partial, int n) {
    __shared__ int wsum[8];
    const int tid = threadIdx.x;
    const int base = blockIdx.x * SCAN_TILE + tid * 4;

    int s = 0;
    if (base + 3 < n) {
        int4 v = *(const int4*)&cnt[base];
        s = v.x + v.y + v.z + v.w;
    } else {
#pragma unroll
        for (int j = 0; j < 4; j++)
            if (base + j < n) s += cnt[base + j];
    }
#pragma unroll
    for (int d = 16; d > 0; d >>= 1)
        s += __shfl_down_sync(0xFFFFFFFFu, s, d);
    if ((tid & 31) == 0) wsum[tid >> 5] = s;
    __syncthreads();
    if (tid < 8) {
        int t = wsum[tid];
#pragma unroll
        for (int d = 4; d > 0; d >>= 1)
            t += __shfl_down_sync(0xFFu, t, d);
        if (tid == 0) partial[blockIdx.x] = t;
    }
}

// ---------------------------------------------------------------------------
// Scan stage B: single-block exclusive scan of nb partials (nb <= 1024)
// ---------------------------------------------------------------------------
__global__ __launch_bounds__(1024, 1)
void scan_partials_kernel(int* __restrict__ partial,
                          int* __restrict__ offs, int nb, int n) {
    __shared__ int wsum[32];
    const int tid = threadIdx.x;
    const int lane = tid & 31;
    const int wid = tid >> 5;

    int v = (tid < nb) ? partial[tid] : 0;
    int incl = v;
#pragma unroll
    for (int d = 1; d < 32; d <<= 1) {
        int t = __shfl_up_sync(0xFFFFFFFFu, incl, d);
        if (lane >= d) incl += t;
    }
    if (lane == 31) wsum[wid] = incl;
    __syncthreads();
    if (wid == 0) {
        int w = wsum[lane];
        int s = w;
#pragma unroll
        for (int d = 1; d < 32; d <<= 1) {
            int t = __shfl_up_sync(0xFFFFFFFFu, s, d);
            if (lane >= d) s += t;
        }
        wsum[lane] = s - w;
    }
    __syncthreads();
    int excl = wsum[wid] + (incl - v);
    if (tid < nb) partial[tid] = excl;
    if (tid == nb - 1) offs[n] = excl + v;
}

// ---------------------------------------------------------------------------
// Scan stage C: per-block local exclusive scan + partial[b]; writes offs AND
// seeds the binscatter cursor.
// ---------------------------------------------------------------------------
__global__ __launch_bounds__(256)
void scan_final_kernel(const int* __restrict__ cnt,
                       const int* __restrict__ partial,
                       int* __restrict__ offs,
                       int* __restrict__ cursor, int n) {
    __shared__ int wsum[8];
    const int tid = threadIdx.x;
    const int lane = tid & 31;
    const int wid = tid >> 5;
    const int base = blockIdx.x * SCAN_TILE + tid * 4;

    int v[4] = {0, 0, 0, 0};
    if (base + 3 < n) {
        int4 t = *(const int4*)&cnt[base];
        v[0] = t.x; v[1] = t.y; v[2] = t.z; v[3] = t.w;
    } else {
#pragma unroll
        for (int j = 0; j < 4; j++)
            if (base + j < n) v[j] = cnt[base + j];
    }
    int tsum = v[0] + v[1] + v[2] + v[3];

    int incl = tsum;
#pragma unroll
    for (int d = 1; d < 32; d <<= 1) {
        int t = __shfl_up_sync(0xFFFFFFFFu, incl, d);
        if (lane >= d) incl += t;
    }
    if (lane == 31) wsum[wid] = incl;
    __syncthreads();
    if (tid < 8) {
        int w = wsum[tid];
        int s = w;
#pragma unroll
        for (int d = 1; d < 8; d <<= 1) {
            int t = __shfl_up_sync(0xFFu, s, d);
            if (tid >= d) s += t;
        }
        wsum[tid] = s - w;
    }
    __syncthreads();

    int excl = partial[blockIdx.x] + wsum[wid] + (incl - tsum);
    int o[4];
    o[0] = excl;
    o[1] = o[0] + v[0];
    o[2] = o[1] + v[1];
    o[3] = o[2] + v[2];
    if (base + 3 < n) {
        *(int4*)&offs[base]   = make_int4(o[0], o[1], o[2], o[3]);
        *(int4*)&cursor[base] = make_int4(o[0], o[1], o[2], o[3]);
    } else {
#pragma unroll
        for (int j = 0; j < 4; j++)
            if (base + j < n) { offs[base + j] = o[j]; cursor[base + j] = o[j]; }
    }
}

// ---------------------------------------------------------------------------
// Kernel 3: bin-scatter with cursor atomics (one pass, no rank array).
// 4 edges per thread, 4 atomics in flight.
// ---------------------------------------------------------------------------
__global__ void binscatter_kernel(const int* __restrict__ erow,
                                  const int* __restrict__ ecol,
                                  const float* __restrict__ evals,
                                  int* __restrict__ cursor,
                                  int2* __restrict__ sorted, int n_edges) {
    int i = blockIdx.x * blockDim.x + threadIdx.x;
    int n4 = n_edges >> 2;
    if (i < n4) {
        int4 r = __ldcs(&((const int4*)erow)[i]);
        int4 c = __ldcs(&((const int4*)ecol)[i]);
        float4 v = __ldcs(&((const float4*)evals)[i]);
        int p0 = atomicAdd(&cursor[r.x], 1);
        int p1 = atomicAdd(&cursor[r.y], 1);
        int p2 = atomicAdd(&cursor[r.z], 1);
        int p3 = atomicAdd(&cursor[r.w], 1);
        __stcs(&sorted[p0], make_int2(c.x, __float_as_int(v.x)));
        __stcs(&sorted[p1], make_int2(c.y, __float_as_int(v.y)));
        __stcs(&sorted[p2], make_int2(c.z, __float_as_int(v.z)));
        __stcs(&sorted[p3], make_int2(c.w, __float_as_int(v.w)));
    }
    if (i < (n_edges & 3)) {
        int j = n4 * 4 + i;
        int pos = atomicAdd(&cursor[erow[j]], 1);
        sorted[pos] = make_int2(ecol[j], __float_as_int(evals[j]));
    }
}

// ---------------------------------------------------------------------------
// Kernel 4: WMMA tensor-core GEMM: support = half(x @ W)
// ---------------------------------------------------------------------------
#define LDW 136
#define SMEM_W_BYTES (128 * LDW * 2)
#define GEMM_SMEM_BYTES (SMEM_W_BYTES + 64 * LDW * 2)

__global__ __launch_bounds__(256)
void wmma_gemm_kernel(const float* __restrict__ x,
                      const float* __restrict__ w,
                      __half* __restrict__ sup, int n_rows) {
    extern __shared__ char smem[];
    __half* Wh = (__half*)smem;
    __half* Xh = (__half*)(smem + SMEM_W_BYTES);
    float*  stage = (float*)smem;

    const int tid = threadIdx.x;
    const int block_row = blockIdx.x * 64;

    for (int i = tid; i < 128 * 128 / 4; i += 256) {
        int r = (i * 4) >> 7;
        int c = (i * 4) & 127;
        float4 f = ((const float4*)w)[i];
        __half2 h[2] = { __floats2half2_rn(f.x, f.y),
                         __floats2half2_rn(f.z, f.w) };
        *(uint2*)&Wh[r * LDW + c] = *(uint2*)h;
    }
    for (int i = tid; i < 64 * 128 / 4; i += 256) {
        int r = (i * 4) >> 7;
        int c = (i * 4) & 127;
        int gr = block_row + r;
        float4 f = make_float4(0.f, 0.f, 0.f, 0.f);
        if (gr < n_rows) f = __ldcs(&((const float4*)x)[gr * 32 + (c >> 2)]);
        __half2 h[2] = { __floats2half2_rn(f.x, f.y),
                         __floats2half2_rn(f.z, f.w) };
        *(uint2*)&Xh[r * LDW + c] = *(uint2*)h;
    }
    __syncthreads();

    const int wid = tid >> 5;
    const int wm = wid & 3;
    const int wn = wid >> 2;

    wmma::fragment<wmma::accumulator, 16, 16, 16, float> acc[4];
#pragma unroll
    for (int j = 0; j < 4; j++) wmma::fill_fragment(acc[j], 0.f);

#pragma unroll
    for (int k = 0; k < 128; k += 16) {
        wmma::fragment<wmma::matrix_a, 16, 16, 16, __half, wmma::row_major> a;
        wmma::load_matrix_sync(a, &Xh[(wm * 16) * LDW + k], LDW);
#pragma unroll
        for (int j = 0; j < 4; j++) {
            wmma::fragment<wmma::matrix_b, 16, 16, 16, __half, wmma::row_major> b;
            wmma::load_matrix_sync(b, &Wh[k * LDW + wn * 64 + j * 16], LDW);
            wmma::mma_sync(acc[j], a, b, acc[j]);
        }
    }

    __syncthreads();
#pragma unroll
    for (int j = 0; j < 4; j++)
        wmma::store_matrix_sync(&stage[(wm * 16) * 128 + wn * 64 + j * 16],
                                acc[j], 128, wmma::mem_row_major);
    __syncthreads();

    for (int i = tid; i < 64 * 128 / 8; i += 256) {
        int r = (i * 8) >> 7;
        int c = (i * 8) & 127;
        int gr = block_row + r;
        if (gr < n_rows) {
            float4 f0 = *(float4*)&stage[r * 128 + c];
            float4 f1 = *(float4*)&stage[r * 128 + c + 4];
            __half2 h[4] = { __floats2half2_rn(f0.x, f0.y),
                             __floats2half2_rn(f0.z, f0.w),
                             __floats2half2_rn(f1.x, f1.y),
                             __floats2half2_rn(f1.z, f1.w) };
            *(uint4*)&sup[(size_t)gr * D + c] = *(uint4*)h;
        }
    }
}

// ---------------------------------------------------------------------------
// Kernel 5: gather — HALF-WARP per row, next-window prefetch pipeline.
// ---------------------------------------------------------------------------
__device__ __forceinline__ void acc_u4(float4& a0, float4& a1, uint4 u, float v) {
    float2 p0 = __half22float2(*(__half2*)&u.x);
    float2 p1 = __half22float2(*(__half2*)&u.y);
    float2 p2 = __half22float2(*(__half2*)&u.z);
    float2 p3 = __half22float2(*(__half2*)&u.w);
    a0.x = fmaf(v, p0.x, a0.x); a0.y = fmaf(v, p0.y, a0.y);
    a0.z = fmaf(v, p1.x, a0.z); a0.w = fmaf(v, p1.y, a0.w);
    a1.x = fmaf(v, p2.x, a1.x); a1.y = fmaf(v, p2.y, a1.y);
    a1.z = fmaf(v, p3.x, a1.z); a1.w = fmaf(v, p3.y, a1.w);
}

__global__ __launch_bounds__(256)
void gather_kernel(const int* __restrict__ offs,
                   const int2* __restrict__ sorted,
                   const __half* __restrict__ sup,
                   const float* __restrict__ bias,
                   float* __restrict__ out, int n_rows) {
    __shared__ int2 stage[16][16];
    const int lane = threadIdx.x & 31;
    const int sub  = lane & 15;
    const int half = lane >> 4;
    const unsigned hmask = half ? 0xFFFF0000u : 0x0000FFFFu;
    const int sidx = ((threadIdx.x >> 5) << 1) | half;
    int warp = (int)((blockIdx.x * (size_t)blockDim.x + threadIdx.x) >> 5);
    const int nhw = (int)(((size_t)gridDim.x * blockDim.x) >> 4);
    const int hw = warp * 2 + half;

    const float4 b0 = ((const float4*)bias)[sub * 2];
    const float4 b1 = ((const float4*)bias)[sub * 2 + 1];

    for (int r = hw; r < n_rows; r += nhw) {
        const int s = offs[r];
        const int e = offs[r + 1];
        float4 a0 = make_float4(0.f, 0.f, 0.f, 0.f);
        float4 a1 = make_float4(0.f, 0.f, 0.f, 0.f);

        // prefetch first window
        int idx = s + sub;
        int2 ed = (idx < e) ? __ldcs(&sorted[idx]) : make_int2(0, 0);

        for (int base = s; base < e; base += 16) {
            stage[sidx][sub] = ed;
            __syncwarp(hmask);
            // prefetch next window while processing this one
            int nidx = base + 16 + sub;
            int2 nx = (nidx < e) ? __ldcs(&sorted[nidx]) : make_int2(0, 0);

            const int m = min(16, e - base);
            int k = 0;
            for (; k + 8 <= m; k += 8) {
                int2 ee[8];
                uint4 uu[8];
#pragma unroll
                for (int j = 0; j < 8; j++) ee[j] = stage[sidx][k + j];
#pragma unroll
                for (int j = 0; j < 8; j++)
                    uu[j] = ((const uint4*)(sup + (size_t)ee[j].x * D))[sub];
#pragma unroll
                for (int j = 0; j < 8; j++)
                    acc_u4(a0, a1, uu[j], __int_as_float(ee[j].y));
            }
            for (; k + 4 <= m; k += 4) {
                int2 ee[4];
                uint4 uu[4];
#pragma unroll
                for (int j = 0; j < 4; j++) ee[j] = stage[sidx][k + j];
#pragma unroll
                for (int j = 0; j < 4; j++)
                    uu[j] = ((const uint4*)(sup + (size_t)ee[j].x * D))[sub];
#pragma unroll
                for (int j = 0; j < 4; j++)
                    acc_u4(a0, a1, uu[j], __int_as_float(ee[j].y));
            }
            for (; k < m; k++) {
                int2 ek = stage[sidx][k];
                uint4 u = ((const uint4*)(sup + (size_t)ek.x * D))[sub];
                acc_u4(a0, a1, u, __int_as_float(ek.y));
            }
            __syncwarp(hmask);
            ed = nx;
        }

        float4 r0 = make_float4(a0.x + b0.x, a0.y + b0.y,
                                a0.z + b0.z, a0.w + b0.w);
        float4 r1 = make_float4(a1.x + b1.x, a1.y + b1.y,
                                a1.z + b1.z, a1.w + b1.w);
        float4* dst = (float4*)(out + (size_t)r * D);
        __stcs(&dst[sub * 2], r0);
        __stcs(&dst[sub * 2 + 1], r1);
    }
}

// ---------------------------------------------------------------------------
// Launch
// ---------------------------------------------------------------------------
extern "C" void kernel_launch(void* const* d_in, const int* in_sizes, int n_in,
                              void* d_out, int out_size) {
    const float* x      = (const float*)d_in[0];
    const float* weight = (const float*)d_in[1];
    const float* bias   = (const float*)d_in[2];
    const int*   erow   = (const int*)d_in[3];
    const int*   ecol   = (const int*)d_in[4];
    const float* evals  = (const float*)d_in[5];
    float* out = (float*)d_out;

    const int n_rows  = in_sizes[0] / D;
    const int n_edges = in_sizes[3];

    __half* sup;  cudaGetSymbolAddress((void**)&sup,  g_support);
    int*    cnt;  cudaGetSymbolAddress((void**)&cnt,  g_count);
    int*    offs; cudaGetSymbolAddress((void**)&offs, g_offs);
    int*    curs; cudaGetSymbolAddress((void**)&curs, g_cursor);
    int2*   srt;  cudaGetSymbolAddress((void**)&srt,  g_sorted);
    int*    part; cudaGetSymbolAddress((void**)&part, g_partial);

    static cudaStream_t s_gemm = nullptr;
    static cudaEvent_t ev_fork = nullptr, ev_join = nullptr;
    if (s_gemm == nullptr) {
        cudaStreamCreateWithFlags(&s_gemm, cudaStreamNonBlocking);
        cudaEventCreateWithFlags(&ev_fork, cudaEventDisableTiming);
        cudaEventCreateWithFlags(&ev_join, cudaEventDisableTiming);
        cudaFuncSetAttribute(wmma_gemm_kernel,
                             cudaFuncAttributeMaxDynamicSharedMemorySize,
                             GEMM_SMEM_BYTES);
    }

    // Fork: GEMM runs concurrently with the CSR build
    cudaEventRecord(ev_fork, 0);
    cudaStreamWaitEvent(s_gemm, ev_fork, 0);
    wmma_gemm_kernel<<<(n_rows + 63) / 64, 256, GEMM_SMEM_BYTES, s_gemm>>>(
        x, weight, sup, n_rows);
    cudaEventRecord(ev_join, s_gemm);

    // CSR build (main stream)
    cudaMemsetAsync(cnt, 0, (size_t)n_rows * sizeof(int), 0);
    {
        int n4 = (n_edges + 3) / 4;
        hist_kernel<<<(n4 + 255) / 256, 256>>>(erow, cnt, n_edges);
    }
    {
        int nb = (n_rows + SCAN_TILE - 1) / SCAN_TILE;
        block_sum_kernel<<<nb, 256>>>(cnt, part, n_rows);
        scan_partials_kernel<<<1, 1024>>>(part, offs, nb, n_rows);
        scan_final_kernel<<<nb, 256>>>(cnt, part, offs, curs, n_rows);
    }
    {
        int n4 = (n_edges + 3) / 4;
        binscatter_kernel<<<(n4 + 255) / 256, 256>>>(erow, ecol, evals, curs,
                                                     srt, n_edges);
    }

    // Join, then gather
    cudaStreamWaitEvent(0, ev_join, 0);
    gather_kernel<<<(n_rows + 15) / 16, 256>>>(offs, srt, sup, bias, out,
                                               n_rows);
}